// round 1
// baseline (speedup 1.0000x reference)
#include <cuda_runtime.h>

#define NN 2048
#define FF 64
#define KK 8
#define GROUP 8

// Scratch: per-feature descending-sorted x values and their node indices.
__device__ float g_sx[FF * NN];
__device__ int   g_si[FF * NN];

__device__ __forceinline__ unsigned key_of(float v) {
    unsigned u = __float_as_uint(v);
    return (u & 0x80000000u) ? ~u : (u | 0x80000000u);
}
__device__ __forceinline__ float val_of(unsigned k) {
    unsigned u = (k & 0x80000000u) ? (k ^ 0x80000000u) : ~k;
    return __uint_as_float(u);
}

// One block per feature f: bitonic sort of 2048 (key|idx) u64s in smem.
__global__ __launch_bounds__(1024) void sort_kernel(const float* __restrict__ x) {
    __shared__ unsigned long long s[NN];
    const int f = blockIdx.x;
    const int tid = threadIdx.x;

    #pragma unroll
    for (int i = tid; i < NN; i += 1024) {
        float v = x[(size_t)i * FF + f];
        s[i] = ((unsigned long long)key_of(v) << 32) | (unsigned)i;
    }
    __syncthreads();

    for (int k = 2; k <= NN; k <<= 1) {
        for (int j = k >> 1; j > 0; j >>= 1) {
            #pragma unroll
            for (int t = tid; t < NN; t += 1024) {
                int ixj = t ^ j;
                if (ixj > t) {
                    unsigned long long a = s[t], b = s[ixj];
                    bool up = ((t & k) == 0);   // ascending run
                    if ((a > b) == up) { s[t] = b; s[ixj] = a; }
                }
            }
            __syncthreads();
        }
    }

    // s[] ascending -> emit descending.
    #pragma unroll
    for (int r = tid; r < NN; r += 1024) {
        unsigned long long e = s[NN - 1 - r];
        g_si[f * NN + r] = (int)(e & 0xFFFFFFFFu);
        g_sx[f * NN + r] = val_of((unsigned)(e >> 32));
    }
}

// blockIdx.y = f, blockIdx.x = m-tile. One thread per m.
// Walk the sorted list, maintain top-8 in registers, early-stop when the
// 8th best t7 >= max(x_cur, 0): since adj in [0,1), every remaining
// product adj*x is <= max(x,0) <= t7.
__global__ __launch_bounds__(256) void topk_kernel(const float* __restrict__ x,
                                                   const float* __restrict__ adj,
                                                   float* __restrict__ out) {
    __shared__ float s_x[NN + GROUP];
    __shared__ int   s_i[NN + GROUP];
    const int f = blockIdx.y;
    const int tid = threadIdx.x;

    #pragma unroll
    for (int i = tid; i < NN; i += 256) {
        s_x[i] = g_sx[f * NN + i];
        s_i[i] = g_si[f * NN + i];
    }
    if (tid < GROUP) { s_x[NN + tid] = -__int_as_float(0x7f800000); s_i[NN + tid] = 0; }
    __syncthreads();

    const int m = blockIdx.x * 256 + tid;
    const float* adjm = adj + m;

    const float NEG_INF = -__int_as_float(0x7f800000);
    float t0 = NEG_INF, t1 = NEG_INF, t2 = NEG_INF, t3 = NEG_INF;
    float t4 = NEG_INF, t5 = NEG_INF, t6 = NEG_INF, t7 = NEG_INF;

    float pa[GROUP];
    #pragma unroll
    for (int u = 0; u < GROUP; u++)
        pa[u] = __ldg(adjm + (size_t)s_i[u] * NN);

    bool done = false;
    for (int ib = 0; ib < NN; ib += GROUP) {
        unsigned alive = __ballot_sync(0xffffffffu, !done);
        if (!alive) break;

        // Prefetch next group (8 independent LDGs in flight).
        float na[GROUP];
        #pragma unroll
        for (int u = 0; u < GROUP; u++) {
            na[u] = 0.0f;
            if (!done) na[u] = __ldg(adjm + (size_t)s_i[ib + GROUP + u] * NN);
        }

        if (!done) {
            float v[GROUP];
            bool any = false;
            #pragma unroll
            for (int u = 0; u < GROUP; u++) {
                v[u] = pa[u] * s_x[ib + u];
                any |= (v[u] > t7);
            }
            if (any) {  // rare slow path: sorted insert via max/min chain
                #pragma unroll
                for (int u = 0; u < GROUP; u++) {
                    float c = v[u];
                    if (c > t7) {
                        float w;
                        w = fmaxf(t0, c); c = fminf(t0, c); t0 = w;
                        w = fmaxf(t1, c); c = fminf(t1, c); t1 = w;
                        w = fmaxf(t2, c); c = fminf(t2, c); t2 = w;
                        w = fmaxf(t3, c); c = fminf(t3, c); t3 = w;
                        w = fmaxf(t4, c); c = fminf(t4, c); t4 = w;
                        w = fmaxf(t5, c); c = fminf(t5, c); t5 = w;
                        w = fmaxf(t6, c); c = fminf(t6, c); t6 = w;
                        t7 = fmaxf(t7, c);
                    }
                }
            }
            // Early stop: everything after this group has x <= s_x[ib+GROUP-1].
            if (t7 >= fmaxf(s_x[ib + GROUP - 1], 0.0f)) done = true;
        }

        #pragma unroll
        for (int u = 0; u < GROUP; u++) pa[u] = na[u];
    }

    // out[m][j][f], j=0 is x[m][f], j=1..8 are the top values desc.
    size_t base = (size_t)m * ((KK + 1) * FF) + f;
    out[base]          = x[(size_t)m * FF + f];
    out[base + 1 * FF] = t0;
    out[base + 2 * FF] = t1;
    out[base + 3 * FF] = t2;
    out[base + 4 * FF] = t3;
    out[base + 5 * FF] = t4;
    out[base + 6 * FF] = t5;
    out[base + 7 * FF] = t6;
    out[base + 8 * FF] = t7;
}

extern "C" void kernel_launch(void* const* d_in, const int* in_sizes, int n_in,
                              void* d_out, int out_size) {
    const float* x   = (const float*)d_in[0];
    const float* adj = (const float*)d_in[1];
    if (n_in >= 2 && in_sizes[0] > in_sizes[1]) {  // defensive: x is the smaller input
        const float* t = x; x = adj; adj = t;
    }
    float* out = (float*)d_out;

    sort_kernel<<<FF, 1024>>>(x);
    topk_kernel<<<dim3(NN / 256, FF), 256>>>(x, adj, out);
}